// round 1
// baseline (speedup 1.0000x reference)
#include <cuda_runtime.h>

// ============================================================================
// MHABlock — algebraically collapsed:
//   qk  = x @ w_qkv[:, :2048] + b_qkv[:2048]          (q | k halves)
//   T[b, h*64+kk, d] = sum_j k[b,j,h,kk] * w_fc[j*16+h, d]
//   y   = x + (1/8) * q @ T + b_fc
//   out = LayerNorm(y) * gamma + beta
// All fp32. Scratch in __device__ globals (no allocations).
// ============================================================================

#define TS 128
#define KS 8

static __device__ float g_qk[4096u * 2048u];      // [B*S, 2048]  (q cols 0..1023, k cols 1024..2047)
static __device__ float g_T[2u * 1024u * 1024u];  // [B, 1024, 1024]
static __device__ float g_y[2u * 2048u * 1024u];  // residual sum, pre-LN

// ---------------------------------------------------------------------------
// G1: g_qk[4096,2048] = x[4096,1024] @ w_qkv[:, 0:2048] (ldb=3072) + b_qkv
// grid (16, 32), 256 threads
// ---------------------------------------------------------------------------
__global__ __launch_bounds__(256) void k_gemm_qk(
    const float* __restrict__ x, const float* __restrict__ w_qkv,
    const float* __restrict__ b_qkv)
{
    __shared__ float As[KS][TS];
    __shared__ float Bs[KS][TS];
    const int t  = threadIdx.x;
    const int bm = blockIdx.y * TS;
    const int bn = blockIdx.x * TS;

    const int arow = t >> 1,  acol = (t & 1) << 2;   // A tile [128 x 8]
    const int brow = t >> 5,  bcol = (t & 31) << 2;  // B tile [8 x 128]
    const int ty8 = (t >> 4) << 3;
    const int tx8 = (t & 15) << 3;

    const float* Ag = x     + (size_t)(bm + arow) * 1024 + acol;
    const float* Bg = w_qkv + (size_t)brow * 3072 + bn + bcol;

    float acc[8][8];
    #pragma unroll
    for (int i = 0; i < 8; i++)
        #pragma unroll
        for (int j = 0; j < 8; j++) acc[i][j] = 0.f;

    for (int k0 = 0; k0 < 1024; k0 += KS) {
        float4 av = *(const float4*)(Ag + k0);
        float4 bv = *(const float4*)(Bg + (size_t)k0 * 3072);
        __syncthreads();
        As[acol + 0][arow] = av.x;
        As[acol + 1][arow] = av.y;
        As[acol + 2][arow] = av.z;
        As[acol + 3][arow] = av.w;
        *(float4*)&Bs[brow][bcol] = bv;
        __syncthreads();
        #pragma unroll
        for (int kk = 0; kk < KS; kk++) {
            float4 a0 = *(const float4*)&As[kk][ty8];
            float4 a1 = *(const float4*)&As[kk][ty8 + 4];
            float4 b0 = *(const float4*)&Bs[kk][tx8];
            float4 b1 = *(const float4*)&Bs[kk][tx8 + 4];
            float ar[8] = {a0.x, a0.y, a0.z, a0.w, a1.x, a1.y, a1.z, a1.w};
            float br[8] = {b0.x, b0.y, b0.z, b0.w, b1.x, b1.y, b1.z, b1.w};
            #pragma unroll
            for (int i = 0; i < 8; i++)
                #pragma unroll
                for (int j = 0; j < 8; j++)
                    acc[i][j] += ar[i] * br[j];
        }
    }

    #pragma unroll
    for (int i = 0; i < 8; i++) {
        const int m = bm + ty8 + i;
        float* Crow = g_qk + (size_t)m * 2048 + bn;
        #pragma unroll
        for (int j = 0; j < 8; j += 4) {
            const int n = tx8 + j;
            float4 o;
            o.x = acc[i][j + 0] + b_qkv[bn + n + 0];
            o.y = acc[i][j + 1] + b_qkv[bn + n + 1];
            o.z = acc[i][j + 2] + b_qkv[bn + n + 2];
            o.w = acc[i][j + 3] + b_qkv[bn + n + 3];
            *(float4*)&Crow[n] = o;
        }
    }
}

// ---------------------------------------------------------------------------
// G2: per head h, both batches stacked:
//   C[m, d] (m: b=m>>6, kk=m&63) = sum_j k[b,j,h,kk] * w_fc[j*16+h, d]
//   -> g_T[(b*1024 + h*64 + kk)*1024 + d]
// grid (8, 1, 16), 256 threads. K = 2048 (j)
// ---------------------------------------------------------------------------
__global__ __launch_bounds__(256) void k_gemm_T(const float* __restrict__ w_fc)
{
    __shared__ float As[KS][TS];
    __shared__ float Bs[KS][TS];
    const int t  = threadIdx.x;
    const int h  = blockIdx.z;
    const int bn = blockIdx.x * TS;          // d block

    const int jrow = t >> 5;                 // 0..7   (j within tile)
    const int col4 = (t & 31) << 2;          // 0..124 (m for A, d for B)
    const int bloc = col4 >> 6;              // batch of this A float4
    const int kk4  = col4 & 63;

    const int ty8 = (t >> 4) << 3;
    const int tx8 = (t & 15) << 3;

    // A[j, m] = g_qk[(bloc*2048 + j)*2048 + 1024 + h*64 + kk4]
    const float* Ag = g_qk + ((size_t)bloc * 2048 + jrow) * 2048 + 1024 + h * 64 + kk4;
    // B[j, d] = w_fc[(j*16 + h)*1024 + bn + col4]
    const float* Bg = w_fc + ((size_t)jrow * 16 + h) * 1024 + bn + col4;

    float acc[8][8];
    #pragma unroll
    for (int i = 0; i < 8; i++)
        #pragma unroll
        for (int j = 0; j < 8; j++) acc[i][j] = 0.f;

    for (int j0 = 0; j0 < 2048; j0 += KS) {
        float4 av = *(const float4*)(Ag + (size_t)j0 * 2048);
        float4 bv = *(const float4*)(Bg + (size_t)j0 * 16 * 1024);
        __syncthreads();
        *(float4*)&As[jrow][col4] = av;
        *(float4*)&Bs[jrow][col4] = bv;
        __syncthreads();
        #pragma unroll
        for (int kk = 0; kk < KS; kk++) {
            float4 a0 = *(const float4*)&As[kk][ty8];
            float4 a1 = *(const float4*)&As[kk][ty8 + 4];
            float4 b0 = *(const float4*)&Bs[kk][tx8];
            float4 b1 = *(const float4*)&Bs[kk][tx8 + 4];
            float ar[8] = {a0.x, a0.y, a0.z, a0.w, a1.x, a1.y, a1.z, a1.w};
            float br[8] = {b0.x, b0.y, b0.z, b0.w, b1.x, b1.y, b1.z, b1.w};
            #pragma unroll
            for (int i = 0; i < 8; i++)
                #pragma unroll
                for (int j = 0; j < 8; j++)
                    acc[i][j] += ar[i] * br[j];
        }
    }

    #pragma unroll
    for (int i = 0; i < 8; i++) {
        const int m   = ty8 + i;
        const int b_o = m >> 6;
        const int kkr = m & 63;
        float* Crow = g_T + ((size_t)b_o * 1024 + h * 64 + kkr) * 1024 + bn;
        #pragma unroll
        for (int j = 0; j < 8; j += 4) {
            float4 o;
            o.x = acc[i][j + 0];
            o.y = acc[i][j + 1];
            o.z = acc[i][j + 2];
            o.w = acc[i][j + 3];
            *(float4*)&Crow[tx8 + j] = o;
        }
    }
}

// ---------------------------------------------------------------------------
// G3: per batch b: g_y[b] = x[b] + 0.125 * q[b] @ T[b] + b_fc
// grid (8, 16, 2), 256 threads. K = 1024
// ---------------------------------------------------------------------------
__global__ __launch_bounds__(256) void k_gemm_out(
    const float* __restrict__ x, const float* __restrict__ b_fc)
{
    __shared__ float As[KS][TS];
    __shared__ float Bs[KS][TS];
    const int t  = threadIdx.x;
    const int b  = blockIdx.z;
    const int bm = blockIdx.y * TS;
    const int bn = blockIdx.x * TS;

    const int arow = t >> 1,  acol = (t & 1) << 2;
    const int brow = t >> 5,  bcol = (t & 31) << 2;
    const int ty8 = (t >> 4) << 3;
    const int tx8 = (t & 15) << 3;

    // A = q part of g_qk (cols 0..1023)
    const float* Ag = g_qk + ((size_t)b * 2048 + bm + arow) * 2048 + acol;
    const float* Bg = g_T  + ((size_t)b * 1024 + brow) * 1024 + bn + bcol;

    float acc[8][8];
    #pragma unroll
    for (int i = 0; i < 8; i++)
        #pragma unroll
        for (int j = 0; j < 8; j++) acc[i][j] = 0.f;

    for (int k0 = 0; k0 < 1024; k0 += KS) {
        float4 av = *(const float4*)(Ag + k0);
        float4 bv = *(const float4*)(Bg + (size_t)k0 * 1024);
        __syncthreads();
        As[acol + 0][arow] = av.x;
        As[acol + 1][arow] = av.y;
        As[acol + 2][arow] = av.z;
        As[acol + 3][arow] = av.w;
        *(float4*)&Bs[brow][bcol] = bv;
        __syncthreads();
        #pragma unroll
        for (int kk = 0; kk < KS; kk++) {
            float4 a0 = *(const float4*)&As[kk][ty8];
            float4 a1 = *(const float4*)&As[kk][ty8 + 4];
            float4 b0 = *(const float4*)&Bs[kk][tx8];
            float4 b1 = *(const float4*)&Bs[kk][tx8 + 4];
            float ar[8] = {a0.x, a0.y, a0.z, a0.w, a1.x, a1.y, a1.z, a1.w};
            float br[8] = {b0.x, b0.y, b0.z, b0.w, b1.x, b1.y, b1.z, b1.w};
            #pragma unroll
            for (int i = 0; i < 8; i++)
                #pragma unroll
                for (int j = 0; j < 8; j++)
                    acc[i][j] += ar[i] * br[j];
        }
    }

    #pragma unroll
    for (int i = 0; i < 8; i++) {
        const int m = bm + ty8 + i;
        const float* xrow = x   + ((size_t)b * 2048 + m) * 1024 + bn;
        float*       yrow = g_y + ((size_t)b * 2048 + m) * 1024 + bn;
        #pragma unroll
        for (int j = 0; j < 8; j += 4) {
            const int n = tx8 + j;
            float4 xv = *(const float4*)&xrow[n];
            float4 o;
            o.x = xv.x + 0.125f * acc[i][j + 0] + b_fc[bn + n + 0];
            o.y = xv.y + 0.125f * acc[i][j + 1] + b_fc[bn + n + 1];
            o.z = xv.z + 0.125f * acc[i][j + 2] + b_fc[bn + n + 2];
            o.w = xv.w + 0.125f * acc[i][j + 3] + b_fc[bn + n + 3];
            *(float4*)&yrow[n] = o;
        }
    }
}

// ---------------------------------------------------------------------------
// LayerNorm over last dim (1024) of g_y -> out. grid 4096, 256 threads.
// ---------------------------------------------------------------------------
__global__ __launch_bounds__(256) void k_ln(
    const float* __restrict__ gamma, const float* __restrict__ beta,
    float* __restrict__ out)
{
    const int row = blockIdx.x;
    const int t   = threadIdx.x;
    const float* yr = g_y + (size_t)row * 1024;

    float4 v = *(const float4*)(yr + t * 4);
    float s  = v.x + v.y + v.z + v.w;
    float sq = v.x * v.x + v.y * v.y + v.z * v.z + v.w * v.w;

    #pragma unroll
    for (int o = 16; o > 0; o >>= 1) {
        s  += __shfl_xor_sync(0xffffffffu, s,  o);
        sq += __shfl_xor_sync(0xffffffffu, sq, o);
    }
    __shared__ float ss[8], ssq[8];
    if ((t & 31) == 0) { ss[t >> 5] = s; ssq[t >> 5] = sq; }
    __syncthreads();
    s = 0.f; sq = 0.f;
    #pragma unroll
    for (int i = 0; i < 8; i++) { s += ss[i]; sq += ssq[i]; }

    const float mean = s * (1.0f / 1024.0f);
    const float var  = sq * (1.0f / 1024.0f) - mean * mean;
    const float rinv = rsqrtf(var + 1e-5f);

    float4 g  = *(const float4*)(gamma + t * 4);
    float4 bt = *(const float4*)(beta  + t * 4);
    float4 o;
    o.x = g.x * (v.x - mean) * rinv + bt.x;
    o.y = g.y * (v.y - mean) * rinv + bt.y;
    o.z = g.z * (v.z - mean) * rinv + bt.z;
    o.w = g.w * (v.w - mean) * rinv + bt.w;
    *(float4*)(out + (size_t)row * 1024 + t * 4) = o;
}

// ---------------------------------------------------------------------------
extern "C" void kernel_launch(void* const* d_in, const int* in_sizes, int n_in,
                              void* d_out, int out_size)
{
    const float* x     = (const float*)d_in[0];
    const float* w_qkv = (const float*)d_in[1];
    const float* b_qkv = (const float*)d_in[2];
    const float* w_fc  = (const float*)d_in[3];
    const float* b_fc  = (const float*)d_in[4];
    const float* gamma = (const float*)d_in[5];
    const float* beta  = (const float*)d_in[6];
    float* out = (float*)d_out;

    k_gemm_qk <<<dim3(16, 32), 256>>>(x, w_qkv, b_qkv);
    k_gemm_T  <<<dim3(8, 1, 16), 256>>>(w_fc);
    k_gemm_out<<<dim3(8, 16, 2), 256>>>(x, b_fc);
    k_ln      <<<4096, 256>>>(gamma, beta, out);
}

// round 14
// speedup vs baseline: 1.1789x; 1.1789x over previous
#include <cuda_runtime.h>
#include <cuda_bf16.h>
#include <stdint.h>

// ============================================================================
// MHABlock collapsed to 3 GEMMs + LN. GEMMs run on warp-level bf16 HMMA
// (mma.sync.m16n8k16 — supported on base sm_103 target; tcgen05 is NOT,
// per ptxas round-9 failure) with hi/lo split error compensation:
//   acc += Ah*Bh + Al*Bh + Ah*Bl   (fp32 register accumulation)
//
//   G1: g_qk[4096,2048] = x @ w_qkv[:, :2048] + b_qkv          K=1024
//   G2: g_T[b,h*64+kk,d] = sum_j k[b,j,h,kk] * w_fc[j*16+h,d]  K=2048
//   G3: g_y = x + 0.125 * q @ T + b_fc                          K=1024
//   LN over last dim -> out
// ============================================================================

static __device__ float g_qk[4096u * 2048u];
static __device__ float g_T[2u * 1024u * 1024u];
static __device__ float g_y[2u * 2048u * 1024u];

#define KP 40  // padded K stride in bf16 elements (20 words -> conflict-free frags)

// split fp32 pair into packed bf16x2 hi + bf16x2 lo (element i in low half)
__device__ __forceinline__ void split_pack(float f0, float f1,
                                           uint32_t& h, uint32_t& l) {
    __nv_bfloat16 h0 = __float2bfloat16_rn(f0);
    __nv_bfloat16 h1 = __float2bfloat16_rn(f1);
    float r0 = f0 - __bfloat162float(h0);
    float r1 = f1 - __bfloat162float(h1);
    __nv_bfloat16 l0 = __float2bfloat16_rn(r0);
    __nv_bfloat16 l1 = __float2bfloat16_rn(r1);
    h = (uint32_t)__bfloat16_as_ushort(h0) |
        ((uint32_t)__bfloat16_as_ushort(h1) << 16);
    l = (uint32_t)__bfloat16_as_ushort(l0) |
        ((uint32_t)__bfloat16_as_ushort(l1) << 16);
}

#define MMA_BF16(c, a, b)                                                      \
    asm volatile(                                                              \
        "mma.sync.aligned.m16n8k16.row.col.f32.bf16.bf16.f32 "                 \
        "{%0,%1,%2,%3}, {%4,%5,%6,%7}, {%8,%9}, {%0,%1,%2,%3};"                \
        : "+f"((c)[0]), "+f"((c)[1]), "+f"((c)[2]), "+f"((c)[3])               \
        : "r"((a)[0]), "r"((a)[1]), "r"((a)[2]), "r"((a)[3]),                  \
          "r"((b)[0]), "r"((b)[1]))

// ---------------------------------------------------------------------------
// MODE 1: g_qk[4096,2048] = x @ w_qkv[:, :2048] + b_qkv      grid (16,32,1)
// MODE 2: per head bz: g_T[(b,kk),d] = sum_j k * w_fc        grid (8,1,16)
// MODE 3: per batch bz: g_y = x + 0.125 * q @ T + b_fc       grid (8,16,2)
// CTA tile 128x128, K-chunk 32, 256 threads (8 warps, 2x4 grid, 64x32/warp).
// ---------------------------------------------------------------------------
template <int MODE>
__global__ __launch_bounds__(256, 1) void k_mma(
    const float* __restrict__ pA, const float* __restrict__ pB,
    const float* __restrict__ pBias, const float* __restrict__ pX)
{
    __shared__ __nv_bfloat16 Ah[128 * KP], Al[128 * KP];
    __shared__ __nv_bfloat16 Bh[128 * KP], Bl[128 * KP];

    const int t    = threadIdx.x;
    const int warp = t >> 5, lane = t & 31;
    const int tid4 = lane >> 2, tm4 = lane & 3;
    const int wm = (warp >> 2) * 64;   // warp row offset within CTA tile
    const int wn = (warp & 3) * 32;    // warp col offset

    const int bn = blockIdx.x * 128;
    const int bm = blockIdx.y * 128;
    const int bz = blockIdx.z;

    float acc[4][4][4];
    #pragma unroll
    for (int i = 0; i < 4; i++)
        #pragma unroll
        for (int j = 0; j < 4; j++)
            #pragma unroll
            for (int r = 0; r < 4; r++) acc[i][j][r] = 0.f;

    const int NCH = (MODE == 2) ? 64 : 32;   // K = 2048 or 1024, chunk 32

    for (int ch = 0; ch < NCH; ch++) {
        const int k0 = ch * 32;
        __syncthreads();   // previous chunk's fragment reads done before restage

        // ---- stage A: SMEM [m][k] hi/lo ----
        if (MODE != 2) {
            const float* Ab = (MODE == 1)
                ? (pA + (size_t)bm * 1024)
                : (g_qk + ((size_t)bz * 2048 + bm) * 2048);
            const int lda = (MODE == 1) ? 1024 : 2048;
            #pragma unroll
            for (int it = 0; it < 8; it++) {
                int fid = t + 256 * it;          // 2048 pairs
                int m = fid >> 4, kq = fid & 15; // k = 2*kq
                float2 v = *(const float2*)(Ab + (size_t)m * lda + k0 + 2 * kq);
                uint32_t h, l; split_pack(v.x, v.y, h, l);
                *(uint32_t*)&Ah[m * KP + 2 * kq] = h;
                *(uint32_t*)&Al[m * KP + 2 * kq] = l;
            }
        } else {
            // A[m=(b,kk)][j]: transpose gather from g_qk's k-half
            #pragma unroll
            for (int it = 0; it < 8; it++) {
                int fid = t + 256 * it;
                int kp = fid >> 7, c = fid & 127;   // k = k0+2*kp, m = c
                size_t gi = ((size_t)(c >> 6) * 2048 + (k0 + 2 * kp)) * 2048
                            + 1024 + (size_t)bz * 64 + (c & 63);
                float f0 = g_qk[gi];
                float f1 = g_qk[gi + 2048];
                uint32_t h, l; split_pack(f0, f1, h, l);
                *(uint32_t*)&Ah[c * KP + 2 * kp] = h;
                *(uint32_t*)&Al[c * KP + 2 * kp] = l;
            }
        }

        // ---- stage B: SMEM [n][k] hi/lo from global k-major [k][n] ----
        #pragma unroll
        for (int it = 0; it < 8; it++) {
            int fid = t + 256 * it;
            int kp = fid >> 7, n = fid & 127;
            int k = k0 + 2 * kp;
            float f0, f1;
            if (MODE == 1) {
                size_t gi = (size_t)k * 3072 + bn + n;
                f0 = pB[gi]; f1 = pB[gi + 3072];
            } else if (MODE == 2) {
                size_t gi = ((size_t)k * 16 + bz) * 1024 + bn + n;
                f0 = pB[gi]; f1 = pB[gi + 16384];
            } else {
                size_t gi = ((size_t)bz * 1024 + k) * 1024 + bn + n;
                f0 = g_T[gi]; f1 = g_T[gi + 1024];
            }
            uint32_t h, l; split_pack(f0, f1, h, l);
            *(uint32_t*)&Bh[n * KP + 2 * kp] = h;
            *(uint32_t*)&Bl[n * KP + 2 * kp] = l;
        }
        __syncthreads();

        // ---- compute: 2 k-steps of 16, 4x4 atoms, 3 mma each ----
        #pragma unroll
        for (int s = 0; s < 2; s++) {
            const int kl = s * 16 + tm4 * 2;   // this thread's k offset
            uint32_t ah[4][4], al_[4][4], bh[4][2], bl_[4][2];
            #pragma unroll
            for (int mb = 0; mb < 4; mb++) {
                int r0 = wm + mb * 16 + tid4;
                ah[mb][0]  = *(const uint32_t*)&Ah[r0 * KP + kl];
                ah[mb][1]  = *(const uint32_t*)&Ah[(r0 + 8) * KP + kl];
                ah[mb][2]  = *(const uint32_t*)&Ah[r0 * KP + kl + 8];
                ah[mb][3]  = *(const uint32_t*)&Ah[(r0 + 8) * KP + kl + 8];
                al_[mb][0] = *(const uint32_t*)&Al[r0 * KP + kl];
                al_[mb][1] = *(const uint32_t*)&Al[(r0 + 8) * KP + kl];
                al_[mb][2] = *(const uint32_t*)&Al[r0 * KP + kl + 8];
                al_[mb][3] = *(const uint32_t*)&Al[(r0 + 8) * KP + kl + 8];
            }
            #pragma unroll
            for (int nb = 0; nb < 4; nb++) {
                int n0 = wn + nb * 8 + tid4;
                bh[nb][0]  = *(const uint32_t*)&Bh[n0 * KP + kl];
                bh[nb][1]  = *(const uint32_t*)&Bh[n0 * KP + kl + 8];
                bl_[nb][0] = *(const uint32_t*)&Bl[n0 * KP + kl];
                bl_[nb][1] = *(const uint32_t*)&Bl[n0 * KP + kl + 8];
            }
            #pragma unroll
            for (int mb = 0; mb < 4; mb++)
                #pragma unroll
                for (int nb = 0; nb < 4; nb++) {
                    MMA_BF16(acc[mb][nb], ah[mb], bh[nb]);
                    MMA_BF16(acc[mb][nb], al_[mb], bh[nb]);
                    MMA_BF16(acc[mb][nb], ah[mb], bl_[nb]);
                }
        }
    }

    // ---- epilogue: fragments -> global (float2 pairs, per MODE) ----
    #pragma unroll
    for (int mb = 0; mb < 4; mb++) {
        #pragma unroll
        for (int nb = 0; nb < 4; nb++) {
            const int rA = wm + mb * 16 + tid4;       // CTA-local rows rA, rA+8
            const int cA = wn + nb * 8 + tm4 * 2;     // CTA-local col pair
            const int n  = bn + cA;
            #pragma unroll
            for (int half = 0; half < 2; half++) {
                const int row = rA + half * 8;
                const float v0 = acc[mb][nb][half * 2 + 0];
                const float v1 = acc[mb][nb][half * 2 + 1];
                if (MODE == 1) {
                    float2 o = make_float2(v0 + pBias[n], v1 + pBias[n + 1]);
                    *(float2*)&g_qk[(size_t)(bm + row) * 2048 + n] = o;
                } else if (MODE == 2) {
                    float2 o = make_float2(v0, v1);
                    size_t r = ((size_t)(row >> 6) * 1024 + bz * 64 + (row & 63));
                    *(float2*)&g_T[r * 1024 + n] = o;
                } else {
                    size_t gi = ((size_t)bz * 2048 + bm + row) * 1024 + n;
                    float2 xv = *(const float2*)&pX[gi];
                    float2 o = make_float2(xv.x + 0.125f * v0 + pBias[n],
                                           xv.y + 0.125f * v1 + pBias[n + 1]);
                    *(float2*)&g_y[gi] = o;
                }
            }
        }
    }
}

// ---------------------------------------------------------------------------
// LayerNorm over last dim (1024) of g_y -> out. grid 4096, 256 threads.
// ---------------------------------------------------------------------------
__global__ __launch_bounds__(256) void k_ln(
    const float* __restrict__ gamma, const float* __restrict__ beta,
    float* __restrict__ out)
{
    const int row = blockIdx.x;
    const int t   = threadIdx.x;
    const float* yr = g_y + (size_t)row * 1024;

    float4 v = *(const float4*)(yr + t * 4);
    float s  = v.x + v.y + v.z + v.w;
    float sq = v.x * v.x + v.y * v.y + v.z * v.z + v.w * v.w;

    #pragma unroll
    for (int o = 16; o > 0; o >>= 1) {
        s  += __shfl_xor_sync(0xffffffffu, s,  o);
        sq += __shfl_xor_sync(0xffffffffu, sq, o);
    }
    __shared__ float ss[8], ssq[8];
    if ((t & 31) == 0) { ss[t >> 5] = s; ssq[t >> 5] = sq; }
    __syncthreads();
    s = 0.f; sq = 0.f;
    #pragma unroll
    for (int i = 0; i < 8; i++) { s += ss[i]; sq += ssq[i]; }

    const float mean = s * (1.0f / 1024.0f);
    const float var  = sq * (1.0f / 1024.0f) - mean * mean;
    const float rinv = rsqrtf(var + 1e-5f);

    float4 g  = *(const float4*)(gamma + t * 4);
    float4 bt = *(const float4*)(beta  + t * 4);
    float4 o;
    o.x = g.x * (v.x - mean) * rinv + bt.x;
    o.y = g.y * (v.y - mean) * rinv + bt.y;
    o.z = g.z * (v.z - mean) * rinv + bt.z;
    o.w = g.w * (v.w - mean) * rinv + bt.w;
    *(float4*)(out + (size_t)row * 1024 + t * 4) = o;
}

// ---------------------------------------------------------------------------
extern "C" void kernel_launch(void* const* d_in, const int* in_sizes, int n_in,
                              void* d_out, int out_size)
{
    const float* x     = (const float*)d_in[0];
    const float* w_qkv = (const float*)d_in[1];
    const float* b_qkv = (const float*)d_in[2];
    const float* w_fc  = (const float*)d_in[3];
    const float* b_fc  = (const float*)d_in[4];
    const float* gamma = (const float*)d_in[5];
    const float* beta  = (const float*)d_in[6];
    float* out = (float*)d_out;

    k_mma<1><<<dim3(16, 32, 1), 256>>>(x, w_qkv, b_qkv, nullptr);
    k_mma<2><<<dim3(8, 1, 16),  256>>>(nullptr, w_fc, nullptr, nullptr);
    k_mma<3><<<dim3(8, 16, 2),  256>>>(nullptr, nullptr, b_fc, x);
    k_ln<<<4096, 256>>>(gamma, beta, out);
}

// round 15
// speedup vs baseline: 2.5773x; 2.1862x over previous
#include <cuda_runtime.h>
#include <cuda_fp16.h>
#include <stdint.h>

// ============================================================================
// MHABlock collapsed to 3 GEMMs + LN on warp-level fp16 HMMA
// (mma.sync.m16n8k16.f32.f16.f16.f32) with 2-term compensation:
//   acc += Ah*Bh + Al*Bh   (A split hi/lo fp16, B single fp16, fp32 accum)
// Residual error ~ A*(B-Bh) ~ 2^-11  -> predicted rel_err ~3.5e-4 (calibrated
// against round-14's bf16 3-term measurement of 1.08e-5 vs 1.5e-5 theory).
//
//   G1: g_qk[4096,2048] = x @ w_qkv[:, :2048] + b_qkv          K=1024
//   G2: g_T[b,h*64+kk,d] = sum_j k[b,j,h,kk] * w_fc[j*16+h,d]  K=2048
//   G3: g_y = x + 0.125 * q @ T + b_fc                          K=1024
//   LN over last dim -> out
// ============================================================================

static __device__ float g_qk[4096u * 2048u];
static __device__ float g_T[2u * 1024u * 1024u];
static __device__ float g_y[2u * 2048u * 1024u];

#define KP 40  // padded K stride in fp16 elements (20 words -> conflict-free frags)

// split fp32 pair into packed fp16x2 hi + fp16x2 lo
__device__ __forceinline__ void split_pack(float f0, float f1,
                                           uint32_t& h, uint32_t& l) {
    __half h0 = __float2half_rn(f0);
    __half h1 = __float2half_rn(f1);
    float r0 = f0 - __half2float(h0);
    float r1 = f1 - __half2float(h1);
    __half l0 = __float2half_rn(r0);
    __half l1 = __float2half_rn(r1);
    h = (uint32_t)__half_as_ushort(h0) | ((uint32_t)__half_as_ushort(h1) << 16);
    l = (uint32_t)__half_as_ushort(l0) | ((uint32_t)__half_as_ushort(l1) << 16);
}
// pack fp32 pair into fp16x2 (hi only, for B)
__device__ __forceinline__ uint32_t pack_h(float f0, float f1) {
    __half h0 = __float2half_rn(f0);
    __half h1 = __float2half_rn(f1);
    return (uint32_t)__half_as_ushort(h0) | ((uint32_t)__half_as_ushort(h1) << 16);
}

#define MMA_F16(c, a, b)                                                       \
    asm volatile(                                                              \
        "mma.sync.aligned.m16n8k16.row.col.f32.f16.f16.f32 "                   \
        "{%0,%1,%2,%3}, {%4,%5,%6,%7}, {%8,%9}, {%0,%1,%2,%3};"                \
        : "+f"((c)[0]), "+f"((c)[1]), "+f"((c)[2]), "+f"((c)[3])               \
        : "r"((a)[0]), "r"((a)[1]), "r"((a)[2]), "r"((a)[3]),                  \
          "r"((b)[0]), "r"((b)[1]))

// ---------------------------------------------------------------------------
// MODE 1: g_qk[4096,2048] = x @ w_qkv[:, :2048] + b_qkv      grid (16,32,1)
// MODE 2: per head bz: g_T[(b,kk),d] = sum_j k * w_fc        grid (8,1,16)
// MODE 3: per batch bz: g_y = x + 0.125 * q @ T + b_fc       grid (8,16,2)
// CTA tile 128x128, K-chunk 32, 256 threads (8 warps, 2x4 grid, 64x32/warp).
// smem 30KB -> 2 CTAs/SM; __launch_bounds__(256,2) caps regs at 128.
// ---------------------------------------------------------------------------
template <int MODE>
__global__ __launch_bounds__(256, 2) void k_mma(
    const float* __restrict__ pA, const float* __restrict__ pB,
    const float* __restrict__ pBias, const float* __restrict__ pX)
{
    __shared__ __half Ah[128 * KP], Al[128 * KP], Bh[128 * KP];

    const int t    = threadIdx.x;
    const int warp = t >> 5, lane = t & 31;
    const int tid4 = lane >> 2, tm4 = lane & 3;
    const int wm = (warp >> 2) * 64;   // warp row offset within CTA tile
    const int wn = (warp & 3) * 32;    // warp col offset

    const int bn = blockIdx.x * 128;
    const int bm = blockIdx.y * 128;
    const int bz = blockIdx.z;

    float acc[4][4][4];
    #pragma unroll
    for (int i = 0; i < 4; i++)
        #pragma unroll
        for (int j = 0; j < 4; j++)
            #pragma unroll
            for (int r = 0; r < 4; r++) acc[i][j][r] = 0.f;

    const int NCH = (MODE == 2) ? 64 : 32;   // K = 2048 or 1024, chunk 32

    for (int ch = 0; ch < NCH; ch++) {
        const int k0 = ch * 32;
        __syncthreads();   // previous chunk's fragment reads done before restage

        // ---- stage A: SMEM [m][k] hi/lo fp16 ----
        if (MODE != 2) {
            const float* Ab = (MODE == 1)
                ? (pA + (size_t)bm * 1024)
                : (g_qk + ((size_t)bz * 2048 + bm) * 2048);
            const int lda = (MODE == 1) ? 1024 : 2048;
            #pragma unroll
            for (int it = 0; it < 8; it++) {
                int fid = t + 256 * it;          // 2048 pairs
                int m = fid >> 4, kq = fid & 15; // k = 2*kq
                float2 v = *(const float2*)(Ab + (size_t)m * lda + k0 + 2 * kq);
                uint32_t h, l; split_pack(v.x, v.y, h, l);
                *(uint32_t*)&Ah[m * KP + 2 * kq] = h;
                *(uint32_t*)&Al[m * KP + 2 * kq] = l;
            }
        } else {
            // A[m=(b,kk)][j]: transpose gather from g_qk's k-half
            #pragma unroll
            for (int it = 0; it < 8; it++) {
                int fid = t + 256 * it;
                int kp = fid >> 7, c = fid & 127;   // k = k0+2*kp, m = c
                size_t gi = ((size_t)(c >> 6) * 2048 + (k0 + 2 * kp)) * 2048
                            + 1024 + (size_t)bz * 64 + (c & 63);
                float f0 = g_qk[gi];
                float f1 = g_qk[gi + 2048];
                uint32_t h, l; split_pack(f0, f1, h, l);
                *(uint32_t*)&Ah[c * KP + 2 * kp] = h;
                *(uint32_t*)&Al[c * KP + 2 * kp] = l;
            }
        }

        // ---- stage B: SMEM [n][k] fp16 hi only ----
        #pragma unroll
        for (int it = 0; it < 8; it++) {
            int fid = t + 256 * it;
            int kp = fid >> 7, n = fid & 127;
            int k = k0 + 2 * kp;
            float f0, f1;
            if (MODE == 1) {
                size_t gi = (size_t)k * 3072 + bn + n;
                f0 = pB[gi]; f1 = pB[gi + 3072];
            } else if (MODE == 2) {
                size_t gi = ((size_t)k * 16 + bz) * 1024 + bn + n;
                f0 = pB[gi]; f1 = pB[gi + 16384];
            } else {
                size_t gi = ((size_t)bz * 1024 + k) * 1024 + bn + n;
                f0 = g_T[gi]; f1 = g_T[gi + 1024];
            }
            *(uint32_t*)&Bh[n * KP + 2 * kp] = pack_h(f0, f1);
        }
        __syncthreads();

        // ---- compute: 2 k-steps of 16; B frags once, A frags per mb-row ----
        #pragma unroll
        for (int s = 0; s < 2; s++) {
            const int kl = s * 16 + tm4 * 2;   // this thread's k offset
            uint32_t bh[4][2];
            #pragma unroll
            for (int nb = 0; nb < 4; nb++) {
                int n0 = wn + nb * 8 + tid4;
                bh[nb][0] = *(const uint32_t*)&Bh[n0 * KP + kl];
                bh[nb][1] = *(const uint32_t*)&Bh[n0 * KP + kl + 8];
            }
            #pragma unroll
            for (int mb = 0; mb < 4; mb++) {
                int r0 = wm + mb * 16 + tid4;
                uint32_t ah[4], al_[4];
                ah[0]  = *(const uint32_t*)&Ah[r0 * KP + kl];
                ah[1]  = *(const uint32_t*)&Ah[(r0 + 8) * KP + kl];
                ah[2]  = *(const uint32_t*)&Ah[r0 * KP + kl + 8];
                ah[3]  = *(const uint32_t*)&Ah[(r0 + 8) * KP + kl + 8];
                al_[0] = *(const uint32_t*)&Al[r0 * KP + kl];
                al_[1] = *(const uint32_t*)&Al[(r0 + 8) * KP + kl];
                al_[2] = *(const uint32_t*)&Al[r0 * KP + kl + 8];
                al_[3] = *(const uint32_t*)&Al[(r0 + 8) * KP + kl + 8];
                #pragma unroll
                for (int nb = 0; nb < 4; nb++) {
                    MMA_F16(acc[mb][nb], ah,  bh[nb]);
                    MMA_F16(acc[mb][nb], al_, bh[nb]);
                }
            }
        }
    }

    // ---- epilogue: fragments -> global (float2 pairs, per MODE) ----
    #pragma unroll
    for (int mb = 0; mb < 4; mb++) {
        #pragma unroll
        for (int nb = 0; nb < 4; nb++) {
            const int rA = wm + mb * 16 + tid4;       // CTA-local rows rA, rA+8
            const int cA = wn + nb * 8 + tm4 * 2;     // CTA-local col pair
            const int n  = bn + cA;
            #pragma unroll
            for (int half = 0; half < 2; half++) {
                const int row = rA + half * 8;
                const float v0 = acc[mb][nb][half * 2 + 0];
                const float v1 = acc[mb][nb][half * 2 + 1];
                if (MODE == 1) {
                    float2 o = make_float2(v0 + pBias[n], v1 + pBias[n + 1]);
                    *(float2*)&g_qk[(size_t)(bm + row) * 2048 + n] = o;
                } else if (MODE == 2) {
                    float2 o = make_float2(v0, v1);
                    size_t r = ((size_t)(row >> 6) * 1024 + bz * 64 + (row & 63));
                    *(float2*)&g_T[r * 1024 + n] = o;
                } else {
                    size_t gi = ((size_t)bz * 2048 + bm + row) * 1024 + n;
                    float2 xv = *(const float2*)&pX[gi];
                    float2 o = make_float2(xv.x + 0.125f * v0 + pBias[n],
                                           xv.y + 0.125f * v1 + pBias[n + 1]);
                    *(float2*)&g_y[gi] = o;
                }
            }
        }
    }
}

// ---------------------------------------------------------------------------
// LayerNorm over last dim (1024) of g_y -> out. grid 4096, 256 threads.
// ---------------------------------------------------------------------------
__global__ __launch_bounds__(256) void k_ln(
    const float* __restrict__ gamma, const float* __restrict__ beta,
    float* __restrict__ out)
{
    const int row = blockIdx.x;
    const int t   = threadIdx.x;
    const float* yr = g_y + (size_t)row * 1024;

    float4 v = *(const float4*)(yr + t * 4);
    float s  = v.x + v.y + v.z + v.w;
    float sq = v.x * v.x + v.y * v.y + v.z * v.z + v.w * v.w;

    #pragma unroll
    for (int o = 16; o > 0; o >>= 1) {
        s  += __shfl_xor_sync(0xffffffffu, s,  o);
        sq += __shfl_xor_sync(0xffffffffu, sq, o);
    }
    __shared__ float ss[8], ssq[8];
    if ((t & 31) == 0) { ss[t >> 5] = s; ssq[t >> 5] = sq; }
    __syncthreads();
    s = 0.f; sq = 0.f;
    #pragma unroll
    for (int i = 0; i < 8; i++) { s += ss[i]; sq += ssq[i]; }

    const float mean = s * (1.0f / 1024.0f);
    const float var  = sq * (1.0f / 1024.0f) - mean * mean;
    const float rinv = rsqrtf(var + 1e-5f);

    float4 g  = *(const float4*)(gamma + t * 4);
    float4 bt = *(const float4*)(beta  + t * 4);
    float4 o;
    o.x = g.x * (v.x - mean) * rinv + bt.x;
    o.y = g.y * (v.y - mean) * rinv + bt.y;
    o.z = g.z * (v.z - mean) * rinv + bt.z;
    o.w = g.w * (v.w - mean) * rinv + bt.w;
    *(float4*)(out + (size_t)row * 1024 + t * 4) = o;
}

// ---------------------------------------------------------------------------
extern "C" void kernel_launch(void* const* d_in, const int* in_sizes, int n_in,
                              void* d_out, int out_size)
{
    const float* x     = (const float*)d_in[0];
    const float* w_qkv = (const float*)d_in[1];
    const float* b_qkv = (const float*)d_in[2];
    const float* w_fc  = (const float*)d_in[3];
    const float* b_fc  = (const float*)d_in[4];
    const float* gamma = (const float*)d_in[5];
    const float* beta  = (const float*)d_in[6];
    float* out = (float*)d_out;

    k_mma<1><<<dim3(16, 32, 1), 256>>>(x, w_qkv, b_qkv, nullptr);
    k_mma<2><<<dim3(8, 1, 16),  256>>>(nullptr, w_fc, nullptr, nullptr);
    k_mma<3><<<dim3(8, 16, 2),  256>>>(nullptr, nullptr, b_fc, x);
    k_ln<<<4096, 256>>>(gamma, beta, out);
}